// round 1
// baseline (speedup 1.0000x reference)
#include <cuda_runtime.h>

// SimilarityMeasureModel: for each (b,p,n) pair, over C=512:
//   l1 = sum |x - y|, l2 = sum (x - y)^2, out = [l1, l2, l1] interleaved.
// Inputs: [B=32, P=3, C=512, N=1024] f32, N contiguous, C strided by N.
// One thread per pair; warp reads contiguous 128B per c-step -> fully coalesced.

static constexpr int B = 32;
static constexpr int P = 3;
static constexpr int C = 512;
static constexpr int N = 1024;
static constexpr int PAIRS = B * P * N;   // 98304

__global__ void __launch_bounds__(256)
sim_measure_kernel(const float* __restrict__ x,
                   const float* __restrict__ y,
                   float* __restrict__ out) {
    const int idx = blockIdx.x * blockDim.x + threadIdx.x;   // 0 .. PAIRS-1
    // idx = b*(P*N) + pp*N + n
    const int r  = idx % (P * N);
    const int n  = r & (N - 1);
    const int pp = r >> 10;               // N = 1024
    const int b  = idx / (P * N);

    // element (b, pp, c, n) lives at ((b*P + pp)*C + c)*N + n
    const size_t base = ((size_t)(b * P + pp)) * C * N + n;

    float l1 = 0.0f;
    float l2 = 0.0f;

    #pragma unroll 8
    for (int c = 0; c < C; ++c) {
        const size_t off = base + (size_t)c * N;
        float a = __ldg(x + off);
        float bb = __ldg(y + off);
        float d = a - bb;
        l1 += fabsf(d);
        l2 = fmaf(d, d, l2);
    }

    // out[b, pp*N + n, {0,1,2}] -> flat index idx*3 + k
    const size_t o = (size_t)idx * 3;
    out[o + 0] = l1;
    out[o + 1] = l2;
    out[o + 2] = l1;
}

extern "C" void kernel_launch(void* const* d_in, const int* in_sizes, int n_in,
                              void* d_out, int out_size) {
    const float* x = (const float*)d_in[0];
    const float* y = (const float*)d_in[1];
    float* out = (float*)d_out;

    const int threads = 256;
    const int blocks = PAIRS / threads;   // 384
    sim_measure_kernel<<<blocks, threads>>>(x, y, out);
}

// round 2
// speedup vs baseline: 1.3678x; 1.3678x over previous
#include <cuda_runtime.h>

// SimilarityMeasureModel on GB300.
// Inputs: x, y [B=32, P=3, C=512, N=1024] f32 (N contiguous).
// Per (b,p,n): l1 = sum_c |x-y|, l2 = sum_c (x-y)^2 ; out = [l1,l2,l1] interleaved.
//
// Strategy: HBM-streaming kernel. float4 loads over n (LDG.128), C split 4 ways
// across thread groups to keep 384 blocks / ~21 warps/SM. ~83KB/SM in flight.

static constexpr int B = 32;
static constexpr int P = 3;
static constexpr int C = 512;
static constexpr int N = 1024;
static constexpr int N4 = N / 4;          // float4 units per row: 256
static constexpr int SEGS = 4;            // C split
static constexpr int CSEG = C / SEGS;     // 128
static constexpr int NV_PER_BLK = 64;     // float4 groups per block -> 256 n values
static constexpr int BLOCKS = (B * P * N) / (NV_PER_BLK * 4);  // 384

__global__ void __launch_bounds__(256, 4)
sim_measure_kernel(const float4* __restrict__ x,
                   const float4* __restrict__ y,
                   float* __restrict__ out) {
    // Block -> (bp, n-quarter)
    const int bid   = blockIdx.x;
    const int bp    = bid >> 2;                 // 0..95  (b*P + p)
    const int nq    = bid & 3;                  // which 256-n chunk
    const int n4off = nq * NV_PER_BLK;          // float4 offset within row

    const int tid = threadIdx.x;
    const int s   = tid >> 6;                   // C-segment 0..3 (2 warps each)
    const int n4  = tid & 63;                   // float4 index within chunk

    // float4-unit index of element (bp, c, n4g)
    const int n4g = n4off + n4;
    size_t idx = ((size_t)bp * C + (size_t)s * CSEG) * N4 + n4g;

    float4 l1 = make_float4(0.f, 0.f, 0.f, 0.f);
    float4 l2 = make_float4(0.f, 0.f, 0.f, 0.f);

    #pragma unroll 4
    for (int c = 0; c < CSEG; ++c) {
        float4 a = __ldg(x + idx);
        float4 b = __ldg(y + idx);
        idx += N4;
        float d0 = a.x - b.x, d1 = a.y - b.y, d2 = a.z - b.z, d3 = a.w - b.w;
        l1.x += fabsf(d0); l1.y += fabsf(d1); l1.z += fabsf(d2); l1.w += fabsf(d3);
        l2.x = fmaf(d0, d0, l2.x); l2.y = fmaf(d1, d1, l2.y);
        l2.z = fmaf(d2, d2, l2.z); l2.w = fmaf(d3, d3, l2.w);
    }

    // Combine the 4 C-segments through shared memory.
    __shared__ float4 sL1[SEGS][NV_PER_BLK];
    __shared__ float4 sL2[SEGS][NV_PER_BLK];
    sL1[s][n4] = l1;
    sL2[s][n4] = l2;
    __syncthreads();

    // 256 threads -> 256 n values of this block; thread t handles n_local = t.
    const int m4 = tid >> 2;      // which float4 group
    const int j  = tid & 3;       // component

    float a1 = 0.f, a2 = 0.f;
    #pragma unroll
    for (int ss = 0; ss < SEGS; ++ss) {
        const float* p1 = (const float*)&sL1[ss][m4];
        const float* p2 = (const float*)&sL2[ss][m4];
        a1 += p1[j];
        a2 += p2[j];
    }

    // pair index = bp*N + nq*256 + tid ; out layout [l1, l2, l1] per pair
    const size_t pair = (size_t)bp * N + (size_t)nq * 256 + tid;
    const size_t o = pair * 3;
    out[o + 0] = a1;
    out[o + 1] = a2;
    out[o + 2] = a1;
}

extern "C" void kernel_launch(void* const* d_in, const int* in_sizes, int n_in,
                              void* d_out, int out_size) {
    const float4* x = (const float4*)d_in[0];
    const float4* y = (const float4*)d_in[1];
    float* out = (float*)d_out;

    sim_measure_kernel<<<BLOCKS, 256>>>(x, y, out);
}